// round 8
// baseline (speedup 1.0000x reference)
#include <cuda_runtime.h>
#include <math.h>

// out = -mean_b log(y[b, argmax(target_b)] + 1e-8)
//       + sum_{b,c} wtab[popc(t_b ^ c)] * y[b,c] / (B*N)
// N = 1024 (10 bits), wtab[0]=0, wtab[p]=6^p (exact in fp32).
//
// Structure: warp-per-row. target rows in registers (prefetched with __ldcs
// after the scan frees them); y rows staged in smem via cp.async (LDGSTS,
// zero register cost), double-buffered, issued one iteration ahead.

#define NCLS   1024
#define SMS    152
#define CPS    7          // smem-limited: 32KB/CTA -> 7 CTAs/SM; 73-reg ceiling
#define BLOCKS (SMS * CPS)
#define TPB    128
#define WPB    (TPB / 32)

__device__ double   g_ce = 0.0;
__device__ double   g_pt = 0.0;
__device__ unsigned g_count = 0;

__device__ __forceinline__ void cp_async16(unsigned sdst, const void* gsrc) {
    asm volatile("cp.async.cg.shared.global [%0], [%1], 16;\n"
                 :: "r"(sdst), "l"(gsrc) : "memory");
}
__device__ __forceinline__ void cp_commit() {
    asm volatile("cp.async.commit_group;\n" ::: "memory");
}
__device__ __forceinline__ void cp_wait1() {
    asm volatile("cp.async.wait_group 1;\n" ::: "memory");
}

__global__ __launch_bounds__(TPB, CPS)
void ce_pt_kernel(const float* __restrict__ y, const float* __restrict__ tgt,
                  float* __restrict__ out, int B) {
    __shared__ float  ybuf[WPB][2][NCLS];    // 32 KB: per-warp double buffer
    __shared__ float  wtab[16];
    __shared__ double s_ce[WPB], s_pt[WPB];

    const int tid  = threadIdx.x;
    const int lane = tid & 31;
    const int wid  = tid >> 5;

    if (tid < 11) {
        float w = 1.0f;
        for (int i = 0; i < tid; i++) w *= 6.0f;   // exact: 6^10 < 2^26
        wtab[tid] = (tid == 0) ? 0.0f : w;
    }
    __syncthreads();

    const int gw = blockIdx.x * WPB + wid;
    const int nw = gridDim.x * WPB;

    float  acc_pt = 0.0f;
    double acc_ce = 0.0;

    // per-lane smem addresses of this warp's two buffers (lane's 16B chunks)
    const unsigned sb0 = (unsigned)__cvta_generic_to_shared(&ybuf[wid][0][0]) + lane * 16;
    const unsigned sb1 = (unsigned)__cvta_generic_to_shared(&ybuf[wid][1][0]) + lane * 16;

    float4 tv[8];

    // ---- prologue: cp.async y(gw) -> buf0 ; LDG target(gw) -> tv ----
    {
        const float4* yrow = (const float4*)(y + (size_t)gw * NCLS) + lane;
        #pragma unroll
        for (int j = 0; j < 8; j++)
            cp_async16(sb0 + j * 32 * 16, yrow + j * 32);
        cp_commit();

        const float4* trow = (const float4*)(tgt + (size_t)gw * NCLS) + lane;
        #pragma unroll
        for (int it = 0; it < 8; it++)
            tv[it] = __ldcs(trow + it * 32);
    }

    int bi = 0;
    for (int r = gw; r < B; r += nw, bi ^= 1) {
        const int  rn       = r + nw;
        const bool has_next = rn < B;                 // warp-uniform

        // ---- argmax scan over tv: packed u64 key (fbits<<32)|(N-1-idx) ----
        // positive uniforms -> IEEE bits monotonic; complemented idx = first-max ties.
        unsigned long long bk = 0ull;
        #pragma unroll
        for (int it = 0; it < 8; it++) {
            int c = (it * 32 + lane) * 4;
            unsigned long long k;
            k = ((unsigned long long)__float_as_uint(tv[it].x) << 32) | (unsigned)(NCLS - 1 - c);
            if (k > bk) bk = k;
            k = ((unsigned long long)__float_as_uint(tv[it].y) << 32) | (unsigned)(NCLS - 2 - c);
            if (k > bk) bk = k;
            k = ((unsigned long long)__float_as_uint(tv[it].z) << 32) | (unsigned)(NCLS - 3 - c);
            if (k > bk) bk = k;
            k = ((unsigned long long)__float_as_uint(tv[it].w) << 32) | (unsigned)(NCLS - 4 - c);
            if (k > bk) bk = k;
        }

        // ---- tv dead: prefetch next target row (regs now free: y is in smem) ----
        if (has_next) {
            const float4* trowN = (const float4*)(tgt + (size_t)rn * NCLS) + lane;
            #pragma unroll
            for (int it = 0; it < 8; it++)
                tv[it] = __ldcs(trowN + it * 32);
        }

        // ---- prefetch next y row into the other buffer (zero register cost) ----
        if (has_next) {
            const float4* yrowN = (const float4*)(y + (size_t)rn * NCLS) + lane;
            const unsigned sbN = bi ? sb0 : sb1;
            #pragma unroll
            for (int j = 0; j < 8; j++)
                cp_async16(sbN + j * 32 * 16, yrowN + j * 32);
        }
        cp_commit();   // always commit (empty group on tail) to keep accounting uniform

        // ---- shuffle reduce bk -> t (both prefetch streams in flight) ----
        #pragma unroll
        for (int off = 16; off; off >>= 1) {
            unsigned long long ok = __shfl_xor_sync(0xFFFFFFFFu, bk, off);
            if (ok > bk) bk = ok;
        }
        const int t = NCLS - 1 - (int)(bk & 0xFFFFFFFFu);

        // ---- y(r) ready: all groups except the newest are complete ----
        cp_wait1();
        __syncwarp();

        const float* yb = &ybuf[wid][bi][0];

        // ---- CE term: single LDS of y[t] ----
        if (lane == 0)
            acc_ce += (double)logf(yb[t] + 1e-8f);

        // ---- weighted sum: factored popcount + 4-way accumulator ILP ----
        const int tb = t >> 2;
        const int tl = t & 3;
        const int d0 = __popc(tl ^ 0), d1 = __popc(tl ^ 1);
        const int d2 = __popc(tl ^ 2), d3 = __popc(tl ^ 3);

        const float4* yb4 = (const float4*)yb;
        float p0 = 0.0f, p1 = 0.0f, p2 = 0.0f, p3 = 0.0f;
        #pragma unroll
        for (int it = 0; it < 8; it++) {
            const int cb = it * 32 + lane;
            const float4 v = yb4[cb];                 // conflict-free LDS.128
            const int pb = __popc(tb ^ cb);
            p0 = fmaf(wtab[pb + d0], v.x, p0);
            p1 = fmaf(wtab[pb + d1], v.y, p1);
            p2 = fmaf(wtab[pb + d2], v.z, p2);
            p3 = fmaf(wtab[pb + d3], v.w, p3);
        }
        acc_pt += (p0 + p1) + (p2 + p3);
    }

    // ---- warp reduce (once) ----
    double dpt = (double)acc_pt;
    #pragma unroll
    for (int off = 16; off; off >>= 1) {
        dpt    += __shfl_xor_sync(0xFFFFFFFFu, dpt,    off);
        acc_ce += __shfl_xor_sync(0xFFFFFFFFu, acc_ce, off);
    }
    if (lane == 0) { s_ce[wid] = acc_ce; s_pt[wid] = dpt; }
    __syncthreads();

    // ---- block reduce + fenced last-block finish ----
    if (tid == 0) {
        double bce = 0.0, bpt = 0.0;
        #pragma unroll
        for (int i = 0; i < WPB; i++) { bce += s_ce[i]; bpt += s_pt[i]; }
        atomicAdd(&g_ce, bce);
        atomicAdd(&g_pt, bpt);
        __threadfence();
        unsigned old = atomicAdd(&g_count, 1u);
        if (old == gridDim.x - 1) {
            double CE = atomicAdd(&g_ce, 0.0);   // L2 read (bypass stale L1)
            double PT = atomicAdd(&g_pt, 0.0);
            out[0] = (float)(-CE / (double)B + PT / ((double)B * (double)NCLS));
            g_ce = 0.0;                           // reset for next graph replay
            g_pt = 0.0;
            g_count = 0u;
        }
    }
}

extern "C" void kernel_launch(void* const* d_in, const int* in_sizes, int n_in,
                              void* d_out, int out_size) {
    const float* y_true = (const float*)d_in[0];
    const float* target = (const float*)d_in[1];
    const int B = in_sizes[0] / NCLS;

    ce_pt_kernel<<<BLOCKS, TPB>>>(y_true, target, (float*)d_out, B);
}

// round 9
// speedup vs baseline: 1.1544x; 1.1544x over previous
#include <cuda_runtime.h>
#include <math.h>

// Two-kernel split:
//   A: t[b] = argmax(target[b,:])          (reads target once, writes g_t)
//   B: out  = -mean log(y[b,t_b]+1e-8) + sum wtab[popc(t_b^c)]*y[b,c]/(B*N)
// N = 1024 (10 bits), wtab[0]=0, wtab[p]=6^p (exact in fp32).
// Each kernel is a single pure stream with interleaved next-row prefetch
// (only one 32-reg row buffer live -> fits CPS=3 / 24 warps/SM).

#define NCLS   1024
#define MAXB   65536
#define SMS    152
#define CPS    3
#define BLOCKS (SMS * CPS)
#define TPB    256
#define WPB    (TPB / 32)

__device__ int      g_t[MAXB];
__device__ double   g_ce = 0.0;
__device__ double   g_pt = 0.0;
__device__ unsigned g_count = 0;

// ---------------------------------------------------------------- kernel A
__global__ __launch_bounds__(TPB, CPS)
void argmax_kernel(const float* __restrict__ tgt, int B) {
    const int tid  = threadIdx.x;
    const int lane = tid & 31;
    const int wid  = tid >> 5;

    const int gw = blockIdx.x * WPB + wid;
    const int nw = gridDim.x * WPB;

    float4 tv[8];
    {
        const float4* trow = (const float4*)(tgt + (size_t)gw * NCLS) + lane;
        #pragma unroll
        for (int it = 0; it < 8; it++)
            tv[it] = __ldcs(trow + it * 32);
    }

    for (int r = gw; r < B; r += nw) {
        const int  rn       = r + nw;
        const bool has_next = rn < B;                 // warp-uniform
        const float4* trowN = (const float4*)(tgt + (size_t)(has_next ? rn : r) * NCLS) + lane;

        // scan with interleaved reload: tv[it] dead right after its keys
        // key = (fbits<<32)|(N-1-idx): positive uniforms -> bits monotonic;
        // complemented idx -> max-key picks FIRST max on ties.
        unsigned long long bk = 0ull;
        #pragma unroll
        for (int it = 0; it < 8; it++) {
            int c = (it * 32 + lane) * 4;
            unsigned long long k;
            k = ((unsigned long long)__float_as_uint(tv[it].x) << 32) | (unsigned)(NCLS - 1 - c);
            if (k > bk) bk = k;
            k = ((unsigned long long)__float_as_uint(tv[it].y) << 32) | (unsigned)(NCLS - 2 - c);
            if (k > bk) bk = k;
            k = ((unsigned long long)__float_as_uint(tv[it].z) << 32) | (unsigned)(NCLS - 3 - c);
            if (k > bk) bk = k;
            k = ((unsigned long long)__float_as_uint(tv[it].w) << 32) | (unsigned)(NCLS - 4 - c);
            if (k > bk) bk = k;
            if (has_next) tv[it] = __ldcs(trowN + it * 32);   // prefetch next row
        }

        // reduce (covered by the 8 in-flight prefetch loads)
        #pragma unroll
        for (int off = 16; off; off >>= 1) {
            unsigned long long ok = __shfl_xor_sync(0xFFFFFFFFu, bk, off);
            if (ok > bk) bk = ok;
        }
        if (lane == 0)
            g_t[r] = NCLS - 1 - (int)(bk & 0xFFFFFFFFu);
    }
}

// ---------------------------------------------------------------- kernel B
__global__ __launch_bounds__(TPB, CPS)
void wsum_kernel(const float* __restrict__ y, float* __restrict__ out, int B) {
    __shared__ float  wtab[16];
    __shared__ double s_ce[WPB], s_pt[WPB];

    const int tid  = threadIdx.x;
    const int lane = tid & 31;
    const int wid  = tid >> 5;

    if (tid < 11) {
        float w = 1.0f;
        for (int i = 0; i < tid; i++) w *= 6.0f;   // exact: 6^10 < 2^26
        wtab[tid] = (tid == 0) ? 0.0f : w;
    }
    __syncthreads();

    const int gw = blockIdx.x * WPB + wid;
    const int nw = gridDim.x * WPB;

    float  acc_pt = 0.0f;
    double acc_ce = 0.0;

    float4 yv[8];
    int tcur;
    {
        const float4* yrow = (const float4*)(y + (size_t)gw * NCLS) + lane;
        #pragma unroll
        for (int it = 0; it < 8; it++)
            yv[it] = __ldcs(yrow + it * 32);
        tcur = g_t[gw];                               // broadcast load
    }

    for (int r = gw; r < B; r += nw) {
        const int  rn       = r + nw;
        const bool has_next = rn < B;                 // warp-uniform
        const float4* yrowN = (const float4*)(y + (size_t)(has_next ? rn : r) * NCLS) + lane;

        const int tn = g_t[has_next ? rn : r];        // prefetch next row's t early
        const int t  = tcur;

        // CE: extract y[t] from the owning lane's registers (before overwrite)
        if (lane == ((t >> 2) & 31)) {
            const int itq = t >> 7;
            const int cq  = t & 3;
            float4 v = yv[0];
            #pragma unroll
            for (int it = 1; it < 8; it++) if (it == itq) v = yv[it];
            float yt = (cq == 0) ? v.x : (cq == 1) ? v.y : (cq == 2) ? v.z : v.w;
            acc_ce += (double)logf(yt + 1e-8f);
        }

        // weighted sum: factored popcount, 4 accumulators, interleaved reload
        const int tb = t >> 2;
        const int tl = t & 3;
        const int d0 = __popc(tl ^ 0), d1 = __popc(tl ^ 1);
        const int d2 = __popc(tl ^ 2), d3 = __popc(tl ^ 3);

        float p0 = 0.0f, p1 = 0.0f, p2 = 0.0f, p3 = 0.0f;
        #pragma unroll
        for (int it = 0; it < 8; it++) {
            const int cb = it * 32 + lane;
            const int pb = __popc(tb ^ cb);
            p0 = fmaf(wtab[pb + d0], yv[it].x, p0);
            p1 = fmaf(wtab[pb + d1], yv[it].y, p1);
            p2 = fmaf(wtab[pb + d2], yv[it].z, p2);
            p3 = fmaf(wtab[pb + d3], yv[it].w, p3);
            if (has_next) yv[it] = __ldcs(yrowN + it * 32);   // prefetch next row
        }
        acc_pt += (p0 + p1) + (p2 + p3);
        tcur = tn;
    }

    // warp reduce (once)
    double dpt = (double)acc_pt;
    #pragma unroll
    for (int off = 16; off; off >>= 1) {
        dpt    += __shfl_xor_sync(0xFFFFFFFFu, dpt,    off);
        acc_ce += __shfl_xor_sync(0xFFFFFFFFu, acc_ce, off);
    }
    if (lane == 0) { s_ce[wid] = acc_ce; s_pt[wid] = dpt; }
    __syncthreads();

    // block reduce + fenced last-block finish
    if (tid == 0) {
        double bce = 0.0, bpt = 0.0;
        #pragma unroll
        for (int i = 0; i < WPB; i++) { bce += s_ce[i]; bpt += s_pt[i]; }
        atomicAdd(&g_ce, bce);
        atomicAdd(&g_pt, bpt);
        __threadfence();
        unsigned old = atomicAdd(&g_count, 1u);
        if (old == gridDim.x - 1) {
            double CE = atomicAdd(&g_ce, 0.0);   // L2 read (bypass stale L1)
            double PT = atomicAdd(&g_pt, 0.0);
            out[0] = (float)(-CE / (double)B + PT / ((double)B * (double)NCLS));
            g_ce = 0.0;                           // reset for next graph replay
            g_pt = 0.0;
            g_count = 0u;
        }
    }
}

extern "C" void kernel_launch(void* const* d_in, const int* in_sizes, int n_in,
                              void* d_out, int out_size) {
    const float* y_true = (const float*)d_in[0];
    const float* target = (const float*)d_in[1];
    const int B = in_sizes[0] / NCLS;

    argmax_kernel<<<BLOCKS, TPB>>>(target, B);
    wsum_kernel  <<<BLOCKS, TPB>>>(y_true, (float*)d_out, B);
}